// round 9
// baseline (speedup 1.0000x reference)
#include <cuda_runtime.h>
#include <cstdint>

using ull = unsigned long long;
#define NROW 1024
#define NDIM 256
#define ROWS 8          // rows per CTA (4 f32x2 pairs per output)
#define ICH  32         // i-lanes per CTA (covers i and i^128 -> 64 outputs)
#define JG   8          // j-interleave groups (one per warp)

__device__ __forceinline__ void fma2(ull& d, ull a, ull b) {
    asm("fma.rn.f32x2 %0, %1, %2, %0;" : "+l"(d) : "l"(a), "l"(b));
}
__device__ __forceinline__ ull mul2(ull a, ull b) {
    ull r; asm("mul.rn.f32x2 %0, %1, %2;" : "=l"(r) : "l"(a), "l"(b));
    return r;
}
// suffix-parity mask: bit p of Uof(j) = parity of bits of j strictly above p.
__host__ __device__ constexpr unsigned Uof(unsigned j) {
    unsigned v = j >> 1; v ^= v >> 1; v ^= v >> 2; v ^= v >> 4;
    return v & 255u;
}
// indicator words over 5-bit m: bit m set iff condition on m holds
__device__ __forceinline__ unsigned subsetWord(unsigned M) {   // m subset of M
    const unsigned magic[5] = {0xAAAAAAAAu, 0xCCCCCCCCu, 0xF0F0F0F0u,
                               0xFF00FF00u, 0xFFFF0000u};
    unsigned w = 0xFFFFFFFFu;
    #pragma unroll
    for (int b = 0; b < 5; ++b)
        if (!((M >> b) & 1u)) w &= ~magic[b];
    return w;
}
__device__ __forceinline__ unsigned supersetWord(unsigned M) { // m superset of M
    const unsigned magic[5] = {0xAAAAAAAAu, 0xCCCCCCCCu, 0xF0F0F0F0u,
                               0xFF00FF00u, 0xFFFF0000u};
    unsigned w = 0xFFFFFFFFu;
    #pragma unroll
    for (int b = 0; b < 5; ++b)
        if ((M >> b) & 1u) w &= magic[b];
    return w;
}

__global__ void __launch_bounds__(256, 2)   // 128-reg ceiling: loose guard only
clifford_kernel(const float* __restrict__ A, const float* __restrict__ B,
                float* __restrict__ out) {
    __shared__ union SmemU {
        struct { float4 As[2][NDIM]; float4 Bs[2][NDIM]; } t;  // 16KB tiles
        ull stage[12][JG][ICH];                                 // 24KB staging
    } sm;

    const unsigned tid = threadIdx.x;
    const unsigned gb  = blockIdx.x >> 2;   // row-group 0..127
    const unsigned ic  = blockIdx.x & 3;    // i-chunk   0..3 (i in [0,128))
    const unsigned rowBase = gb * ROWS;
    const unsigned ibase   = ic * ICH;

    // ---- fill: thread tid stages component j = tid for 8 rows ----
    {
        const unsigned j = tid;
        const float sg = (__popc(j & Uof(j)) & 1) ? -1.0f : 1.0f;
        float av[8], bv[8];
        #pragma unroll
        for (int r = 0; r < 8; ++r) {
            av[r] = A[(size_t)(rowBase + r) * NDIM + j] * sg;
            bv[r] = B[(size_t)(rowBase + r) * NDIM + j];
        }
        sm.t.As[0][j] = make_float4(av[0], av[1], av[2], av[3]);
        sm.t.As[1][j] = make_float4(av[4], av[5], av[6], av[7]);
        sm.t.Bs[0][j] = make_float4(bv[0], bv[1], bv[2], bv[3]);
        sm.t.Bs[1][j] = make_float4(bv[4], bv[5], bv[6], bv[7]);
    }
    __syncthreads();

    const unsigned il = tid & 31;
    const unsigned jg = tid >> 5;
    const unsigned i  = ibase + il;         // i < 128; second output is i^128
    const unsigned Mh = i >> 3;             // 0..15
    const unsigned il3 = i & 7u;

    // hoisted per-thread sign pieces
    const unsigned xbase  = i ^ jg;
    const unsigned ph     = (unsigned)(__popc(i & Uof(jg)) & 1) << 31;
    const unsigned sgb1   = 0x3f800000u ^ ph;                   // output i
    const unsigned sgflip = (unsigned)(__popc(i) & 1) << 31;    // sg2 = sg1 ^ sgflip

    // ---- sign indicator word: bit m = parity(i & U(8m)) (XOR-linear in m) ----
    unsigned Ws = 0;
    {
        const unsigned magic[5] = {0xAAAAAAAAu, 0xCCCCCCCCu, 0xF0F0F0F0u,
                                   0xFF00FF00u, 0xFFFF0000u};
        #pragma unroll
        for (int b = 0; b < 5; ++b)
            if (__popc(i & ((8u << b) - 1u)) & 1) Ws ^= magic[b];
    }

    // ---- predicate indicator words over m (j = 8m|jg, pair j^128) ----
    const bool condW = ((jg & ~i & 7u) == 0u);   // jg subset of i (low 3)
    const bool condD = ((i & jg) == 0u);         // low-3 disjoint
    const bool condS = ((il3 & ~jg & 7u) == 0u); // i low-3 subset of jg
    const unsigned subRep = subsetWord(Mh | 16u);            // (m&15) subset Mh
    const unsigned dRep   = subsetWord((~Mh & 15u) | 16u);   // (m&15) disjoint Mh
    const unsigned supRep = supersetWord(Mh);                // (m&15) superset Mh
    const unsigned Wwe2  = condW ? subRep : 0u;              // wedge, output i^128
    const unsigned Wwe1  = Wwe2 & 0xFFFFu;                   // wedge, output i (j7==0)
    const unsigned Winn1 = (condD ? dRep : 0u) | (condS ? supRep : 0u);
    const unsigned Winn2 = (condD ? (dRep & 0xFFFF0000u) : 0u)
                         | (condS ? (supRep & 0xFFFFu) : 0u);

    // acc[out*12 + prod*4 + pair]
    ull acc[24];
    #pragma unroll
    for (int q = 0; q < 24; ++q) acc[q] = 0ull;

    const ulonglong2* __restrict__ Asp0 = reinterpret_cast<const ulonglong2*>(&sm.t.As[0][0]);
    const ulonglong2* __restrict__ Asp1 = reinterpret_cast<const ulonglong2*>(&sm.t.As[1][0]);
    const ulonglong2* __restrict__ Bsp0 = reinterpret_cast<const ulonglong2*>(&sm.t.Bs[0][0]);
    const ulonglong2* __restrict__ Bsp1 = reinterpret_cast<const ulonglong2*>(&sm.t.Bs[1][0]);

    #pragma unroll 4
    for (unsigned m = 0; m < 32; ++m) {
        const unsigned j  = (m << 3) | jg;
        const unsigned x  = xbase ^ (m << 3);

        const unsigned sb  = (Ws << (31u - m)) & 0x80000000u;  // sign bit for this m
        const unsigned sg1 = sgb1 ^ sb;
        const unsigned sg2 = sg1 ^ sgflip;
        const ull sg1_64 = ((ull)sg1 << 32) | sg1;
        const ull sg2_64 = ((ull)sg2 << 32) | sg2;

        const bool pw1 = (Wwe1  >> m) & 1u;
        const bool pw2 = (Wwe2  >> m) & 1u;
        const bool pi1 = (Winn1 >> m) & 1u;
        const bool pi2 = (Winn2 >> m) & 1u;

        const ulonglong2 a1lo = Asp0[j];          // broadcasts
        const ulonglong2 a1hi = Asp1[j];
        const ulonglong2 a2lo = Asp0[j ^ 128u];
        const ulonglong2 a2hi = Asp1[j ^ 128u];
        const ulonglong2 blo  = Bsp0[x];          // conflict-free gathers, shared
        const ulonglong2 bhi  = Bsp1[x];

        ull t;
        // output i
        t = mul2(a1lo.x, blo.x);
        fma2(acc[0], t, sg1_64); if (pw1) fma2(acc[4], t, sg1_64); if (pi1) fma2(acc[8],  t, sg1_64);
        t = mul2(a1lo.y, blo.y);
        fma2(acc[1], t, sg1_64); if (pw1) fma2(acc[5], t, sg1_64); if (pi1) fma2(acc[9],  t, sg1_64);
        t = mul2(a1hi.x, bhi.x);
        fma2(acc[2], t, sg1_64); if (pw1) fma2(acc[6], t, sg1_64); if (pi1) fma2(acc[10], t, sg1_64);
        t = mul2(a1hi.y, bhi.y);
        fma2(acc[3], t, sg1_64); if (pw1) fma2(acc[7], t, sg1_64); if (pi1) fma2(acc[11], t, sg1_64);
        // output i^128 (terms j^128), reusing b
        t = mul2(a2lo.x, blo.x);
        fma2(acc[12], t, sg2_64); if (pw2) fma2(acc[16], t, sg2_64); if (pi2) fma2(acc[20], t, sg2_64);
        t = mul2(a2lo.y, blo.y);
        fma2(acc[13], t, sg2_64); if (pw2) fma2(acc[17], t, sg2_64); if (pi2) fma2(acc[21], t, sg2_64);
        t = mul2(a2hi.x, bhi.x);
        fma2(acc[14], t, sg2_64); if (pw2) fma2(acc[18], t, sg2_64); if (pi2) fma2(acc[22], t, sg2_64);
        t = mul2(a2hi.y, bhi.y);
        fma2(acc[15], t, sg2_64); if (pw2) fma2(acc[19], t, sg2_64); if (pi2) fma2(acc[23], t, sg2_64);
    }

    // ---- deterministic cross-warp reduction, two half-passes (24KB stage) ----
    #pragma unroll
    for (unsigned ih = 0; ih < 2; ++ih) {
        __syncthreads();             // tiles (ih=0) / prior stage (ih=1) consumed
        #pragma unroll
        for (int q = 0; q < 12; ++q)
            sm.stage[q][jg][il] = acc[ih * 12 + q];
        __syncthreads();

        const unsigned qh0 = (tid >> 5) * 3;        // 3 outputs per thread
        #pragma unroll
        for (int k = 0; k < 3; ++k) {
            const unsigned qh   = qh0 + k;          // 0..23 = prod*8 + row
            const unsigned prod = qh >> 3;
            const unsigned r    = qh & 7;           // row 0..7
            const unsigned q    = prod * 4 + (r >> 1);
            const unsigned hf   = r & 1;
            const float* sp = reinterpret_cast<const float*>(&sm.stage[q][0][0]);
            float s = 0.0f;
            #pragma unroll
            for (int w = 0; w < 8; ++w)
                s += sp[(w * ICH + il) * 2 + hf];
            out[(size_t)prod * (NROW * NDIM)
                + (size_t)(rowBase + r) * NDIM
                + ih * 128u + ibase + il] = s;
        }
    }
}

extern "C" void kernel_launch(void* const* d_in, const int* in_sizes, int n_in,
                              void* d_out, int out_size) {
    const float* A = (const float*)d_in[0];
    const float* B = (const float*)d_in[1];
    float* out = (float*)d_out;
    // 1024 rows / 8 rows-per-CTA = 128 row-groups; x 4 i-chunks = 512 CTAs
    clifford_kernel<<<512, 256>>>(A, B, out);
}

// round 10
// speedup vs baseline: 1.1287x; 1.1287x over previous
#include <cuda_runtime.h>
#include <cstdint>

using ull = unsigned long long;
#define NROW 1024
#define NDIM 256
#define ROWS 8          // rows per CTA
#define ICH  32         // i-chunk per CTA
#define JG   8          // j-interleave groups (one per warp)

__device__ __forceinline__ void fma2(ull& d, ull a, ull b) {
    asm("fma.rn.f32x2 %0, %1, %2, %0;" : "+l"(d) : "l"(a), "l"(b));
}
__device__ __forceinline__ ull mul2(ull a, ull b) {
    ull r; asm("mul.rn.f32x2 %0, %1, %2;" : "=l"(r) : "l"(a), "l"(b));
    return r;
}
// suffix-parity mask: bit p of Uof(j) = parity of bits of j strictly above p.
// XOR-linear: Uof(a^b) = Uof(a)^Uof(b).
__host__ __device__ constexpr unsigned Uof(unsigned j) {
    unsigned v = j >> 1; v ^= v >> 1; v ^= v >> 2; v ^= v >> 4;
    return v & 255u;
}
// indicator words over 5-bit m: bit m set iff condition on m holds
__device__ __forceinline__ unsigned subsetWord(unsigned M) {   // m subset of M
    const unsigned magic[5] = {0xAAAAAAAAu, 0xCCCCCCCCu, 0xF0F0F0F0u,
                               0xFF00FF00u, 0xFFFF0000u};
    unsigned w = 0xFFFFFFFFu;
    #pragma unroll
    for (int b = 0; b < 5; ++b)
        if (!((M >> b) & 1u)) w &= ~magic[b];
    return w;
}
__device__ __forceinline__ unsigned supersetWord(unsigned M) { // m superset of M
    const unsigned magic[5] = {0xAAAAAAAAu, 0xCCCCCCCCu, 0xF0F0F0F0u,
                               0xFF00FF00u, 0xFFFF0000u};
    unsigned w = 0xFFFFFFFFu;
    #pragma unroll
    for (int b = 0; b < 5; ++b)
        if ((M >> b) & 1u) w &= magic[b];
    return w;
}

__global__ void __launch_bounds__(256)
clifford_kernel(const float* __restrict__ A, const float* __restrict__ B,
                float* __restrict__ out) {
    __shared__ float4 As[2][NDIM];          // sign-folded A, rows 0-3 / 4-7
    __shared__ float4 Bs[2][NDIM];
    __shared__ ull    stage[12][JG][ICH];   // reduction staging

    const unsigned tid = threadIdx.x;
    const unsigned gb  = blockIdx.x >> 3;   // row-group 0..127
    const unsigned ic  = blockIdx.x & 7;    // i-chunk   0..7
    const unsigned rowBase = gb * ROWS;
    const unsigned ibase   = ic * ICH;

    // ---- fill: thread tid stages component slot j = tid for all 8 rows ----
    {
        const unsigned j = tid;
        const float sg = (__popc(j & Uof(j)) & 1) ? -1.0f : 1.0f;  // fold c_j
        float av[8], bv[8];
        #pragma unroll
        for (int r = 0; r < 8; ++r) {
            av[r] = A[(size_t)(rowBase + r) * NDIM + j] * sg;
            bv[r] = B[(size_t)(rowBase + r) * NDIM + j];
        }
        As[0][j] = make_float4(av[0], av[1], av[2], av[3]);
        As[1][j] = make_float4(av[4], av[5], av[6], av[7]);
        Bs[0][j] = make_float4(bv[0], bv[1], bv[2], bv[3]);
        Bs[1][j] = make_float4(bv[4], bv[5], bv[6], bv[7]);
    }
    __syncthreads();

    const unsigned il = tid & 31;           // lane -> i within chunk
    const unsigned jg = tid >> 5;           // warp -> j residue (mod 8)
    const unsigned i  = ibase + il;         // full 0..255
    const unsigned Mh = i >> 3;             // 0..31
    const unsigned xb = i ^ jg;

    // ---- sign indicator word: bit m = parity(i & U(8m|jg)) (c_j in tile) ----
    unsigned Ws = 0;
    {
        const unsigned magic[5] = {0xAAAAAAAAu, 0xCCCCCCCCu, 0xF0F0F0F0u,
                                   0xFF00FF00u, 0xFFFF0000u};
        #pragma unroll
        for (int b = 0; b < 5; ++b)
            if (__popc(i & ((8u << b) - 1u)) & 1) Ws ^= magic[b];
        if (__popc(i & Uof(jg)) & 1) Ws = ~Ws;   // fold jg part
    }

    // ---- predicate indicator words over m (j = 8m|jg) ----
    const bool condW = ((jg & ~i & 7u) == 0u);     // jg subset of i low-3
    const bool condD = ((i & jg & 7u) == 0u);      // low-3 disjoint
    const bool condS = ((i & 7u & ~jg) == 0u);     // i low-3 subset of jg
    const unsigned Wwe  = condW ? subsetWord(Mh) : 0u;                 // j subset of i
    const unsigned Winn = (condD ? subsetWord(~Mh & 31u) : 0u)         // disjoint
                        | (condS ? supersetWord(Mh) : 0u);             // i subset of j

    ull acc[12];                                 // [prod*4 + pair]
    #pragma unroll
    for (int q = 0; q < 12; ++q) acc[q] = 0ull;

    const ulonglong2* __restrict__ As0 = reinterpret_cast<const ulonglong2*>(&As[0][0]);
    const ulonglong2* __restrict__ As1 = reinterpret_cast<const ulonglong2*>(&As[1][0]);
    const ulonglong2* __restrict__ Bs0 = reinterpret_cast<const ulonglong2*>(&Bs[0][0]);
    const ulonglong2* __restrict__ Bs1 = reinterpret_cast<const ulonglong2*>(&Bs[1][0]);

    #pragma unroll
    for (unsigned m = 0; m < 32; ++m) {
        const unsigned j = (m << 3) | jg;        // compile-time offsets
        const unsigned x = xb ^ (m << 3);

        // sign: bit m of Ws -> float sign bit
        const unsigned sb = (Ws << (31u - m)) & 0x80000000u;
        const unsigned sg = 0x3f800000u ^ sb;               // ±1.0f
        // masks: all-ones/zero smears from word bits
        const unsigned mwm = (unsigned)((int)(Wwe  << (31u - m)) >> 31);
        const unsigned mim = (unsigned)((int)(Winn << (31u - m)) >> 31);
        const unsigned mw = sg & mwm;                       // ±1 or 0
        const unsigned mi = sg & mim;

        const ull sg2 = ((ull)sg << 32) | sg;
        const ull mw2 = ((ull)mw << 32) | mw;
        const ull mi2 = ((ull)mi << 32) | mi;

        const ulonglong2 a0 = As0[j];   // broadcast (warp-uniform j)
        const ulonglong2 a1 = As1[j];
        const ulonglong2 b0 = Bs0[x];   // conflict-free lane permutation
        const ulonglong2 b1 = Bs1[x];

        ull t0 = mul2(a0.x, b0.x);
        fma2(acc[0], t0, sg2); fma2(acc[4], t0, mw2); fma2(acc[8],  t0, mi2);
        ull t1 = mul2(a0.y, b0.y);
        fma2(acc[1], t1, sg2); fma2(acc[5], t1, mw2); fma2(acc[9],  t1, mi2);
        ull t2 = mul2(a1.x, b1.x);
        fma2(acc[2], t2, sg2); fma2(acc[6], t2, mw2); fma2(acc[10], t2, mi2);
        ull t3 = mul2(a1.y, b1.y);
        fma2(acc[3], t3, sg2); fma2(acc[7], t3, mw2); fma2(acc[11], t3, mi2);
    }

    // ---- deterministic cross-warp reduction over the 8 j-groups ----
    #pragma unroll
    for (int q = 0; q < 12; ++q)
        stage[q][jg][il] = acc[q];
    __syncthreads();

    {
        const unsigned qh0 = (tid >> 5) * 3;        // 3 outputs per thread
        #pragma unroll
        for (int k = 0; k < 3; ++k) {
            const unsigned qh   = qh0 + k;          // 0..23 = prod*8 + row
            const unsigned prod = qh >> 3;
            const unsigned r    = qh & 7;
            const unsigned pair = r >> 1;
            const unsigned hf   = r & 1;
            const float* sp = reinterpret_cast<const float*>(&stage[prod * 4 + pair][0][0]);
            float s = 0.0f;
            #pragma unroll
            for (int w = 0; w < 8; ++w)
                s += sp[(w * ICH + il) * 2 + hf];
            out[(size_t)prod * (NROW * NDIM) + (size_t)(rowBase + r) * NDIM + ibase + il] = s;
        }
    }
}

extern "C" void kernel_launch(void* const* d_in, const int* in_sizes, int n_in,
                              void* d_out, int out_size) {
    const float* A = (const float*)d_in[0];
    const float* B = (const float*)d_in[1];
    float* out = (float*)d_out;
    // 1024 rows / 8 rows-per-CTA = 128 row-groups; x 8 i-chunks = 1024 CTAs
    clifford_kernel<<<1024, 256>>>(A, B, out);
}

// round 11
// speedup vs baseline: 1.2318x; 1.0914x over previous
#include <cuda_runtime.h>
#include <cstdint>

using ull = unsigned long long;
#define NROW 1024
#define NDIM 256
#define ROWS 8          // rows per CTA
#define ICH  32         // i-chunk per CTA
#define JG   8          // j-interleave groups (one per warp)

__device__ __forceinline__ void fma2(ull& d, ull a, ull b) {
    asm("fma.rn.f32x2 %0, %1, %2, %0;" : "+l"(d) : "l"(a), "l"(b));
}
__device__ __forceinline__ ull mul2(ull a, ull b) {
    ull r; asm("mul.rn.f32x2 %0, %1, %2;" : "=l"(r) : "l"(a), "l"(b));
    return r;
}
// suffix-parity mask: bit p of Uof(j) = parity of bits of j strictly above p.
// XOR-linear: Uof(a^b) = Uof(a)^Uof(b).
__host__ __device__ constexpr unsigned Uof(unsigned j) {
    unsigned v = j >> 1; v ^= v >> 1; v ^= v >> 2; v ^= v >> 4;
    return v & 255u;
}
// indicator words over 5-bit m: bit m set iff condition on m holds
__device__ __forceinline__ unsigned subsetWord(unsigned M) {   // m subset of M
    const unsigned magic[5] = {0xAAAAAAAAu, 0xCCCCCCCCu, 0xF0F0F0F0u,
                               0xFF00FF00u, 0xFFFF0000u};
    unsigned w = 0xFFFFFFFFu;
    #pragma unroll
    for (int b = 0; b < 5; ++b)
        if (!((M >> b) & 1u)) w &= ~magic[b];
    return w;
}
__device__ __forceinline__ unsigned supersetWord(unsigned M) { // m superset of M
    const unsigned magic[5] = {0xAAAAAAAAu, 0xCCCCCCCCu, 0xF0F0F0F0u,
                               0xFF00FF00u, 0xFFFF0000u};
    unsigned w = 0xFFFFFFFFu;
    #pragma unroll
    for (int b = 0; b < 5; ++b)
        if ((M >> b) & 1u) w &= magic[b];
    return w;
}

__global__ void __launch_bounds__(256, 4)   // 64-reg cap: natural is 66, 3% trim
clifford_kernel(const float* __restrict__ A, const float* __restrict__ B,
                float* __restrict__ out) {
    __shared__ float4 As[2][NDIM];          // sign-folded A, rows 0-3 / 4-7
    __shared__ float4 Bs[2][NDIM];
    __shared__ ull    stage[12][JG][ICH];   // reduction staging

    const unsigned tid = threadIdx.x;
    const unsigned gb  = blockIdx.x >> 3;   // row-group 0..127
    const unsigned ic  = blockIdx.x & 7;    // i-chunk   0..7
    const unsigned rowBase = gb * ROWS;
    const unsigned ibase   = ic * ICH;

    // ---- fill: thread tid stages component slot j = tid for all 8 rows ----
    {
        const unsigned j = tid;
        const float sg = (__popc(j & Uof(j)) & 1) ? -1.0f : 1.0f;  // fold c_j
        float av[8], bv[8];
        #pragma unroll
        for (int r = 0; r < 8; ++r) {
            av[r] = A[(size_t)(rowBase + r) * NDIM + j] * sg;
            bv[r] = B[(size_t)(rowBase + r) * NDIM + j];
        }
        As[0][j] = make_float4(av[0], av[1], av[2], av[3]);
        As[1][j] = make_float4(av[4], av[5], av[6], av[7]);
        Bs[0][j] = make_float4(bv[0], bv[1], bv[2], bv[3]);
        Bs[1][j] = make_float4(bv[4], bv[5], bv[6], bv[7]);
    }
    __syncthreads();

    const unsigned il = tid & 31;           // lane -> i within chunk
    const unsigned jg = tid >> 5;           // warp -> j residue (mod 8)
    const unsigned i  = ibase + il;         // full 0..255
    const unsigned Mh = i >> 3;             // 0..31
    const unsigned xb = i ^ jg;

    // ---- sign indicator word: bit m = parity(i & U(8m|jg)) (c_j in tile) ----
    unsigned Ws = 0;
    {
        const unsigned magic[5] = {0xAAAAAAAAu, 0xCCCCCCCCu, 0xF0F0F0F0u,
                                   0xFF00FF00u, 0xFFFF0000u};
        #pragma unroll
        for (int b = 0; b < 5; ++b)
            if (__popc(i & ((8u << b) - 1u)) & 1) Ws ^= magic[b];
        if (__popc(i & Uof(jg)) & 1) Ws = ~Ws;   // fold jg part
    }

    // ---- predicate indicator words over m (j = 8m|jg) ----
    const bool condW = ((jg & ~i & 7u) == 0u);     // jg subset of i low-3
    const bool condD = ((i & jg & 7u) == 0u);      // low-3 disjoint
    const bool condS = ((i & 7u & ~jg) == 0u);     // i low-3 subset of jg
    const unsigned Wwe  = condW ? subsetWord(Mh) : 0u;                 // j subset of i
    const unsigned Winn = (condD ? subsetWord(~Mh & 31u) : 0u)         // disjoint
                        | (condS ? supersetWord(Mh) : 0u);             // i subset of j

    ull acc[12];                                 // [prod*4 + pair]
    #pragma unroll
    for (int q = 0; q < 12; ++q) acc[q] = 0ull;

    const ulonglong2* __restrict__ As0 = reinterpret_cast<const ulonglong2*>(&As[0][0]);
    const ulonglong2* __restrict__ As1 = reinterpret_cast<const ulonglong2*>(&As[1][0]);
    const ulonglong2* __restrict__ Bs0 = reinterpret_cast<const ulonglong2*>(&Bs[0][0]);
    const ulonglong2* __restrict__ Bs1 = reinterpret_cast<const ulonglong2*>(&Bs[1][0]);

    #pragma unroll
    for (unsigned m = 0; m < 32; ++m) {
        const unsigned j = (m << 3) | jg;        // compile-time offsets
        const unsigned x = xb ^ (m << 3);

        // sign: bit m of Ws -> float sign bit
        const unsigned sb = (Ws << (31u - m)) & 0x80000000u;
        const unsigned sg = 0x3f800000u ^ sb;               // ±1.0f
        // masks: all-ones/zero smears from word bits
        const unsigned mwm = (unsigned)((int)(Wwe  << (31u - m)) >> 31);
        const unsigned mim = (unsigned)((int)(Winn << (31u - m)) >> 31);
        const unsigned mw = sg & mwm;                       // ±1 or 0
        const unsigned mi = sg & mim;

        const ull sg2 = ((ull)sg << 32) | sg;
        const ull mw2 = ((ull)mw << 32) | mw;
        const ull mi2 = ((ull)mi << 32) | mi;

        const ulonglong2 a0 = As0[j];   // broadcast (warp-uniform j)
        const ulonglong2 a1 = As1[j];
        const ulonglong2 b0 = Bs0[x];   // conflict-free lane permutation
        const ulonglong2 b1 = Bs1[x];

        ull t0 = mul2(a0.x, b0.x);
        fma2(acc[0], t0, sg2); fma2(acc[4], t0, mw2); fma2(acc[8],  t0, mi2);
        ull t1 = mul2(a0.y, b0.y);
        fma2(acc[1], t1, sg2); fma2(acc[5], t1, mw2); fma2(acc[9],  t1, mi2);
        ull t2 = mul2(a1.x, b1.x);
        fma2(acc[2], t2, sg2); fma2(acc[6], t2, mw2); fma2(acc[10], t2, mi2);
        ull t3 = mul2(a1.y, b1.y);
        fma2(acc[3], t3, sg2); fma2(acc[7], t3, mw2); fma2(acc[11], t3, mi2);
    }

    // ---- deterministic cross-warp reduction over the 8 j-groups ----
    #pragma unroll
    for (int q = 0; q < 12; ++q)
        stage[q][jg][il] = acc[q];
    __syncthreads();

    {
        const unsigned qh0 = (tid >> 5) * 3;        // 3 outputs per thread
        #pragma unroll
        for (int k = 0; k < 3; ++k) {
            const unsigned qh   = qh0 + k;          // 0..23 = prod*8 + row
            const unsigned prod = qh >> 3;
            const unsigned r    = qh & 7;
            const unsigned pair = r >> 1;
            const unsigned hf   = r & 1;
            const float* sp = reinterpret_cast<const float*>(&stage[prod * 4 + pair][0][0]);
            float s = 0.0f;
            #pragma unroll
            for (int w = 0; w < 8; ++w)
                s += sp[(w * ICH + il) * 2 + hf];
            out[(size_t)prod * (NROW * NDIM) + (size_t)(rowBase + r) * NDIM + ibase + il] = s;
        }
    }
}

extern "C" void kernel_launch(void* const* d_in, const int* in_sizes, int n_in,
                              void* d_out, int out_size) {
    const float* A = (const float*)d_in[0];
    const float* B = (const float*)d_in[1];
    float* out = (float*)d_out;
    // 1024 rows / 8 rows-per-CTA = 128 row-groups; x 8 i-chunks = 1024 CTAs
    clifford_kernel<<<1024, 256>>>(A, B, out);
}